// round 6
// baseline (speedup 1.0000x reference)
#include <cuda_runtime.h>
#include <cstdint>

typedef unsigned long long u64;

__device__ float g_u_tgt;

// Compute u(target) = MLP(6.2562059, 6.2562059) once per launch.
__global__ void utgt_kernel(const float* __restrict__ W1, const float* __restrict__ b1,
                            const float* __restrict__ W2, const float* __restrict__ b2,
                            const float* __restrict__ W3, const float* __restrict__ b3) {
    __shared__ float h1[64];
    __shared__ float part[64];
    int t = threadIdx.x;  // 64 threads
    const float tt = 6.2562059f;
    float h = fmaf(W1[2 * t], tt, fmaf(W1[2 * t + 1], tt, b1[t]));
    h1[t] = fmaxf(h, 0.f);
    __syncthreads();
    float acc = b2[t];
#pragma unroll
    for (int k = 0; k < 64; k++) acc = fmaf(W2[t * 64 + k], h1[k], acc);
    part[t] = W3[t] * fmaxf(acc, 0.f);
    __syncthreads();
    if (t == 0) {
        float s = b3[0];
#pragma unroll
        for (int k = 0; k < 64; k++) s += part[k];
        g_u_tgt = s;
    }
}

__device__ __forceinline__ u64 pack2(float lo, float hi) {
    return ((u64)__float_as_uint(hi) << 32) | (u64)__float_as_uint(lo);
}
__device__ __forceinline__ float lo32(u64 v) { return __uint_as_float((unsigned)(v & 0xffffffffu)); }
__device__ __forceinline__ float hi32(u64 v) { return __uint_as_float((unsigned)(v >> 32)); }

#define SWZ(o) ((o) ^ (((o) >> 3) & 0x70u))

// Dynamic smem: [0, 32768) h tile  u64 h[m][128 tokens]  (1024 B rows, SW128)
//               [32768, 65536) w tile u64 w[m][64 j] padded to 1024 B rows, SW128
#define H_OFF 0u
#define W_OFF 32768u
#define DSMEM 65536

__global__ void __launch_bounds__(128) netc_kernel(
    const float* __restrict__ x, const float* __restrict__ y,
    const float* __restrict__ ex, const float* __restrict__ ey,
    const float* __restrict__ W1, const float* __restrict__ b1,
    const float* __restrict__ W2, const float* __restrict__ b2,
    const float* __restrict__ W3, const float* __restrict__ b3,
    float* __restrict__ out, int n) {
    extern __shared__ char dsm[];
    __shared__ float w1s[128], b1s[64], b2s[64], w3s[64];

    unsigned base = (unsigned)__cvta_generic_to_shared(dsm);
    int tid = threadIdx.x;

    w1s[tid] = W1[tid];
    if (tid < 64) { b1s[tid] = b1[tid]; b2s[tid] = b2[tid]; w3s[tid] = W3[tid]; }

    // W2 -> w tile: u64 (W2[j][2m], W2[j][2m+1]) at SWZ(m*1024 + j*8).
    // p indexed so consecutive lanes hit consecutive j (coalesced gmem, spread smem).
    for (int p = tid; p < 2048; p += 128) {
        int j = p & 63, m = p >> 6;
        float2 v = ((const float2*)W2)[j * 32 + m];
        u64 pk = pack2(v.x, v.y);
        unsigned off = W_OFF + (unsigned)(m * 1024) + SWZ((unsigned)(j * 8));
        asm volatile("st.shared.b64 [%0], %1;" :: "r"(base + off), "l"(pk) : "memory");
    }

    // Layer 1: one token per thread; h packed (k even, k odd) per u64, m-major.
    int token0 = blockIdx.x * 128;
    int mytok = token0 + tid;
    int ic = min(mytok, n - 1);
    float a = x[ic] + ex[ic], c = y[ic] + ey[ic];
#pragma unroll
    for (int m = 0; m < 32; m++) {
        int k0 = 2 * m, k1 = 2 * m + 1;
        float h0 = fmaxf(fmaf(w1s[2 * k0], a, fmaf(w1s[2 * k0 + 1], c, b1s[k0])), 0.f);
        float h1 = fmaxf(fmaf(w1s[2 * k1], a, fmaf(w1s[2 * k1 + 1], c, b1s[k1])), 0.f);
        unsigned off = H_OFF + (unsigned)(m * 1024) + SWZ((unsigned)(tid * 8));
        asm volatile("st.shared.b64 [%0], %1;" :: "r"(base + off), "l"(pack2(h0, h1)) : "memory");
    }
    __syncthreads();

    // GEMM: thread (tg, jg) computes tokens 8tg..8tg+7 x neurons 8jg..8jg+7.
    int tg = tid >> 3, jg = tid & 7;
    u64 acc[64];
#pragma unroll
    for (int i = 0; i < 64; i++) acc[i] = 0ull;

    // Row-local swizzled chunk offsets (mask depends only on bits 7-9 of the
    // in-row offset since rows are 1024 B).
    unsigned hq[4], wq[4];
#pragma unroll
    for (int q = 0; q < 4; q++) {
        hq[q] = base + H_OFF + SWZ((unsigned)(tg * 64 + q * 16));
        wq[q] = base + W_OFF + SWZ((unsigned)(jg * 64 + q * 16));
    }

#pragma unroll 2
    for (int m = 0; m < 32; m++) {
        u64 hv[8], wv[8];
        unsigned rm = (unsigned)(m * 1024);
#pragma unroll
        for (int q = 0; q < 4; q++) {
            asm("ld.shared.v2.b64 {%0, %1}, [%2];"
                : "=l"(hv[2 * q]), "=l"(hv[2 * q + 1]) : "r"(hq[q] + rm));
        }
#pragma unroll
        for (int q = 0; q < 4; q++) {
            asm("ld.shared.v2.b64 {%0, %1}, [%2];"
                : "=l"(wv[2 * q]), "=l"(wv[2 * q + 1]) : "r"(wq[q] + rm));
        }
        // Grouped by h operand: 8 consecutive FFMA2 share hv[t] (reuse cache).
#pragma unroll
        for (int t = 0; t < 8; t++) {
#pragma unroll
            for (int j = 0; j < 8; j++) {
                asm("fma.rn.f32x2 %0, %1, %2, %0;"
                    : "+l"(acc[t * 8 + j]) : "l"(hv[t]), "l"(wv[j]));
            }
        }
    }

    // Epilogue: per token partial over this thread's 8 j, then butterfly over jg.
    float b2v[8], w3v[8];
#pragma unroll
    for (int j = 0; j < 8; j++) { b2v[j] = b2s[jg * 8 + j]; w3v[j] = w3s[jg * 8 + j]; }

    float o[8];
#pragma unroll
    for (int t = 0; t < 8; t++) {
        float s = 0.f;
#pragma unroll
        for (int j = 0; j < 8; j++) {
            float v = lo32(acc[t * 8 + j]) + hi32(acc[t * 8 + j]) + b2v[j];
            s = fmaf(w3v[j], fmaxf(v, 0.f), s);
        }
        o[t] = s;
    }
#pragma unroll
    for (int d = 1; d < 8; d <<= 1) {
#pragma unroll
        for (int t = 0; t < 8; t++) o[t] += __shfl_xor_sync(0xffffffffu, o[t], d);
    }

    if (jg == 0) {
        float bias3 = b3[0];
        float ut = g_u_tgt;
#pragma unroll
        for (int t = 0; t < 8; t++) {
            int i = token0 + tg * 8 + t;
            if (i < n) {
                float xv = x[i], yv = y[i];
                float u = o[t] + bias3 - ut;
                float xs = xv * 0.1f, ys = yv * 0.1f;
                float x2 = xs * xs, y2 = ys * ys;
                float ivx = 1.f / (0.25f + x2);
                float ivy = 1.f / (0.25f + y2);
                float hx = x2 * ivx, hy = y2 * ivy;
                float gx = 0.25f * ivx, gy = 0.25f * ivy;
                float dx = 10.f * (hx + 0.2f * gy - 1.1f * xs + u * hx);
                float dy = 10.f * (hy + 0.2f * gx - 1.1f * ys);
                out[i] = dx;
                out[n + i] = dy;
                out[2 * n + i] = -dx;
                out[3 * n + i] = -dy;
            }
        }
    }
}

extern "C" void kernel_launch(void* const* d_in, const int* in_sizes, int n_in,
                              void* d_out, int out_size) {
    const float* x  = (const float*)d_in[0];
    const float* y  = (const float*)d_in[1];
    const float* ex = (const float*)d_in[2];
    const float* ey = (const float*)d_in[3];
    const float* W1 = (const float*)d_in[4];
    const float* b1 = (const float*)d_in[5];
    const float* W2 = (const float*)d_in[6];
    const float* b2 = (const float*)d_in[7];
    const float* W3 = (const float*)d_in[8];
    const float* b3 = (const float*)d_in[9];
    int n = in_sizes[0];

    static bool attr_set = false;
    if (!attr_set) {
        cudaFuncSetAttribute(netc_kernel,
                             cudaFuncAttributeMaxDynamicSharedMemorySize, DSMEM);
        attr_set = true;
    }

    utgt_kernel<<<1, 64>>>(W1, b1, W2, b2, W3, b3);
    int blocks = (n + 127) / 128;
    netc_kernel<<<blocks, 128, DSMEM>>>(x, y, ex, ey, W1, b1, W2, b2, W3, b3,
                                        (float*)d_out, n);
}

// round 7
// speedup vs baseline: 1.7559x; 1.7559x over previous
#include <cuda_runtime.h>
#include <cuda_bf16.h>
#include <cstdint>

__device__ float g_u_tgt;

// Compute u(target) = MLP(6.2562059, 6.2562059) once per launch.
__global__ void utgt_kernel(const float* __restrict__ W1, const float* __restrict__ b1,
                            const float* __restrict__ W2, const float* __restrict__ b2,
                            const float* __restrict__ W3, const float* __restrict__ b3) {
    __shared__ float h1[64];
    __shared__ float part[64];
    int t = threadIdx.x;
    const float tt = 6.2562059f;
    float h = fmaf(W1[2 * t], tt, fmaf(W1[2 * t + 1], tt, b1[t]));
    h1[t] = fmaxf(h, 0.f);
    __syncthreads();
    float acc = b2[t];
#pragma unroll
    for (int k = 0; k < 64; k++) acc = fmaf(W2[t * 64 + k], h1[k], acc);
    part[t] = W3[t] * fmaxf(acc, 0.f);
    __syncthreads();
    if (t == 0) {
        float s = b3[0];
#pragma unroll
        for (int k = 0; k < 64; k++) s += part[k];
        g_u_tgt = s;
    }
}

__device__ __forceinline__ uint32_t bf16x2(float lo, float hi) {
    __nv_bfloat16 l = __float2bfloat16(lo), h = __float2bfloat16(hi);
    return ((uint32_t)__bfloat16_as_ushort(h) << 16) | __bfloat16_as_ushort(l);
}

// smem tiles, 144-byte row pitch (9x16B -> conflict-free ldmatrix, no swizzle)
#define AH_OFF 0u
#define AL_OFF 18432u
#define BH_OFF 36864u
#define BL_OFF 46080u
#define DSMEM  55296

#define LDSM4(r0, r1, r2, r3, a) \
    asm volatile("ldmatrix.sync.aligned.m8n8.x4.shared.b16 {%0,%1,%2,%3}, [%4];" \
                 : "=r"(r0), "=r"(r1), "=r"(r2), "=r"(r3) : "r"(a))

#define MMA16816(d, a, b0v, b1v) \
    asm volatile("mma.sync.aligned.m16n8k16.row.col.f32.bf16.bf16.f32 " \
                 "{%0,%1,%2,%3}, {%4,%5,%6,%7}, {%8,%9}, {%0,%1,%2,%3};" \
                 : "+f"(d[0]), "+f"(d[1]), "+f"(d[2]), "+f"(d[3]) \
                 : "r"(a[0]), "r"(a[1]), "r"(a[2]), "r"(a[3]), "r"(b0v), "r"(b1v))

__global__ void __launch_bounds__(128) netc_kernel(
    const float* __restrict__ x, const float* __restrict__ y,
    const float* __restrict__ ex, const float* __restrict__ ey,
    const float* __restrict__ W1, const float* __restrict__ b1,
    const float* __restrict__ W2, const float* __restrict__ b2,
    const float* __restrict__ W3, const float* __restrict__ b3,
    float* __restrict__ out, int n) {
    extern __shared__ char dsm[];
    __shared__ float w1s[128], b1s[64], b2s[64], w3s[64];

    unsigned base = (unsigned)__cvta_generic_to_shared(dsm);
    int tid = threadIdx.x;
    int lane = tid & 31, wid = tid >> 5;
    int q = lane & 3, g = lane >> 2;

    w1s[tid] = W1[tid];
    if (tid < 64) { b1s[tid] = b1[tid]; b2s[tid] = b2[tid]; w3s[tid] = W3[tid]; }

    // W2 -> bf16 hi/lo B tiles: row j (144 B pitch), word kw = k/2 (bf16x2).
    for (int p = tid; p < 2048; p += 128) {
        int j = p >> 5, kw = p & 31;
        float2 v = ((const float2*)W2)[p];
        __nv_bfloat16 hx = __float2bfloat16(v.x);
        __nv_bfloat16 hy = __float2bfloat16(v.y);
        float fx = __bfloat162float(hx), fy = __bfloat162float(hy);
        uint32_t whi = ((uint32_t)__bfloat16_as_ushort(hy) << 16) | __bfloat16_as_ushort(hx);
        uint32_t wlo = bf16x2(v.x - fx, v.y - fy);
        unsigned off = (unsigned)(j * 144 + kw * 4);
        asm volatile("st.shared.b32 [%0], %1;" :: "r"(base + BH_OFF + off), "r"(whi) : "memory");
        asm volatile("st.shared.b32 [%0], %1;" :: "r"(base + BL_OFF + off), "r"(wlo) : "memory");
    }

    // Layer 1 (fp32): token per thread; split h -> bf16 hi/lo A tiles.
    int token0 = blockIdx.x * 128;
    int ic = min(token0 + tid, n - 1);
    float av = x[ic] + ex[ic], cv = y[ic] + ey[ic];
    float h[64];
#pragma unroll
    for (int k = 0; k < 64; k++)
        h[k] = fmaxf(fmaf(w1s[2 * k], av, fmaf(w1s[2 * k + 1], cv, b1s[k])), 0.f);

#pragma unroll
    for (int c4 = 0; c4 < 8; c4++) {
        uint32_t hiw[4], low[4];
#pragma unroll
        for (int w = 0; w < 4; w++) {
            int kw = c4 * 4 + w;
            float v0 = h[2 * kw], v1 = h[2 * kw + 1];
            __nv_bfloat16 h0 = __float2bfloat16(v0), h1 = __float2bfloat16(v1);
            float f0 = __bfloat162float(h0), f1 = __bfloat162float(h1);
            hiw[w] = ((uint32_t)__bfloat16_as_ushort(h1) << 16) | __bfloat16_as_ushort(h0);
            low[w] = bf16x2(v0 - f0, v1 - f1);
        }
        unsigned off = (unsigned)(tid * 144 + c4 * 16);
        asm volatile("st.shared.v4.b32 [%0], {%1,%2,%3,%4};"
                     :: "r"(base + AH_OFF + off), "r"(hiw[0]), "r"(hiw[1]), "r"(hiw[2]), "r"(hiw[3]) : "memory");
        asm volatile("st.shared.v4.b32 [%0], {%1,%2,%3,%4};"
                     :: "r"(base + AL_OFF + off), "r"(low[0]), "r"(low[1]), "r"(low[2]), "r"(low[3]) : "memory");
    }
    __syncthreads();

    // GEMM: warp covers tokens [wid*32, wid*32+32): 2 m-tiles x 8 n-tiles.
    float d[2][8][4];
#pragma unroll
    for (int mt = 0; mt < 2; mt++)
#pragma unroll
        for (int nt = 0; nt < 8; nt++)
#pragma unroll
            for (int r = 0; r < 4; r++) d[mt][nt][r] = 0.f;

    // ldmatrix lane addressing precomputed parts
    int a_row_in = (lane & 15);           // row within m16 tile
    int a_koff = (lane >> 4) * 16;        // 0 or 16 bytes (k half)
    int b_row = (lane & 7);               // j within n8 tile
    int b_coff = (lane >> 3) * 16;        // 0/16/32/48 bytes (4 k-chunks)

#pragma unroll
    for (int split = 0; split < 3; split++) {
        unsigned abase = base + ((split == 2) ? AL_OFF : AH_OFF);
        unsigned bbase = base + ((split == 1) ? BL_OFF : BH_OFF);

        // B fragments: all 8 n-tiles x 4 k-steps (2 regs each) = 64 regs.
        uint32_t bfr[8][8];
#pragma unroll
        for (int nt = 0; nt < 8; nt++) {
#pragma unroll
            for (int ksp = 0; ksp < 2; ksp++) {
                unsigned addr = bbase + (unsigned)((nt * 8 + b_row) * 144 + ksp * 64) + b_coff;
                LDSM4(bfr[nt][ksp * 4 + 0], bfr[nt][ksp * 4 + 1],
                      bfr[nt][ksp * 4 + 2], bfr[nt][ksp * 4 + 3], addr);
            }
        }

#pragma unroll
        for (int mt = 0; mt < 2; mt++) {
            uint32_t afr[4][4];
#pragma unroll
            for (int ks = 0; ks < 4; ks++) {
                int row = wid * 32 + mt * 16 + a_row_in;
                unsigned addr = abase + (unsigned)(row * 144 + ks * 32) + a_koff;
                LDSM4(afr[ks][0], afr[ks][1], afr[ks][2], afr[ks][3], addr);
            }
#pragma unroll
            for (int nt = 0; nt < 8; nt++) {
#pragma unroll
                for (int ks = 0; ks < 4; ks++) {
                    int bi = (ks >> 1) * 4 + (ks & 1) * 2;
                    MMA16816(d[mt][nt], afr[ks], bfr[nt][bi], bfr[nt][bi + 1]);
                }
            }
        }
    }

    // Epilogue: layer 3 per row, reduce over the 4 lanes of each row group.
    float ut = g_u_tgt, bias3 = b3[0];
#pragma unroll
    for (int mt = 0; mt < 2; mt++) {
        float s0 = 0.f, s1 = 0.f;  // rows g and g+8
#pragma unroll
        for (int nt = 0; nt < 8; nt++) {
            int j0 = nt * 8 + 2 * q, j1 = j0 + 1;
            float w30 = w3s[j0], w31 = w3s[j1];
            float b20 = b2s[j0], b21 = b2s[j1];
            s0 = fmaf(w30, fmaxf(d[mt][nt][0] + b20, 0.f), s0);
            s0 = fmaf(w31, fmaxf(d[mt][nt][1] + b21, 0.f), s0);
            s1 = fmaf(w30, fmaxf(d[mt][nt][2] + b20, 0.f), s1);
            s1 = fmaf(w31, fmaxf(d[mt][nt][3] + b21, 0.f), s1);
        }
        s0 += __shfl_xor_sync(0xffffffffu, s0, 1);
        s0 += __shfl_xor_sync(0xffffffffu, s0, 2);
        s1 += __shfl_xor_sync(0xffffffffu, s1, 1);
        s1 += __shfl_xor_sync(0xffffffffu, s1, 2);

        if (q == 0) {
#pragma unroll
            for (int half = 0; half < 2; half++) {
                int ti = token0 + wid * 32 + mt * 16 + g + half * 8;
                float s = half ? s1 : s0;
                if (ti < n) {
                    float xv = x[ti], yv = y[ti];
                    float u = s + bias3 - ut;
                    float xs = xv * 0.1f, ys = yv * 0.1f;
                    float x2 = xs * xs, y2 = ys * ys;
                    float ivx = 1.f / (0.25f + x2);
                    float ivy = 1.f / (0.25f + y2);
                    float hx = x2 * ivx, hy = y2 * ivy;
                    float gx = 0.25f * ivx, gy = 0.25f * ivy;
                    float dx = 10.f * (hx + 0.2f * gy - 1.1f * xs + u * hx);
                    float dy = 10.f * (hy + 0.2f * gx - 1.1f * ys);
                    out[ti] = dx;
                    out[n + ti] = dy;
                    out[2 * n + ti] = -dx;
                    out[3 * n + ti] = -dy;
                }
            }
        }
    }
}

extern "C" void kernel_launch(void* const* d_in, const int* in_sizes, int n_in,
                              void* d_out, int out_size) {
    const float* x  = (const float*)d_in[0];
    const float* y  = (const float*)d_in[1];
    const float* ex = (const float*)d_in[2];
    const float* ey = (const float*)d_in[3];
    const float* W1 = (const float*)d_in[4];
    const float* b1 = (const float*)d_in[5];
    const float* W2 = (const float*)d_in[6];
    const float* b2 = (const float*)d_in[7];
    const float* W3 = (const float*)d_in[8];
    const float* b3 = (const float*)d_in[9];
    int n = in_sizes[0];

    static bool attr_set = false;
    if (!attr_set) {
        cudaFuncSetAttribute(netc_kernel,
                             cudaFuncAttributeMaxDynamicSharedMemorySize, DSMEM);
        attr_set = true;
    }

    utgt_kernel<<<1, 64>>>(W1, b1, W2, b2, W3, b3);
    int blocks = (n + 127) / 128;
    netc_kernel<<<blocks, 128, DSMEM>>>(x, y, ex, ey, W1, b1, W2, b2, W3, b3,
                                        (float*)d_out, n);
}

// round 8
// speedup vs baseline: 3.1699x; 1.8053x over previous
#include <cuda_runtime.h>
#include <cuda_bf16.h>
#include <cstdint>

__device__ float g_u_tgt;

// Compute u(target) = MLP(6.2562059, 6.2562059) once per launch.
__global__ void utgt_kernel(const float* __restrict__ W1, const float* __restrict__ b1,
                            const float* __restrict__ W2, const float* __restrict__ b2,
                            const float* __restrict__ W3, const float* __restrict__ b3) {
    __shared__ float h1[64];
    __shared__ float part[64];
    int t = threadIdx.x;
    const float tt = 6.2562059f;
    float h = fmaf(W1[2 * t], tt, fmaf(W1[2 * t + 1], tt, b1[t]));
    h1[t] = fmaxf(h, 0.f);
    __syncthreads();
    float acc = b2[t];
#pragma unroll
    for (int k = 0; k < 64; k++) acc = fmaf(W2[t * 64 + k], h1[k], acc);
    part[t] = W3[t] * fmaxf(acc, 0.f);
    __syncthreads();
    if (t == 0) {
        float s = b3[0];
#pragma unroll
        for (int k = 0; k < 64; k++) s += part[k];
        g_u_tgt = s;
    }
}

__device__ __forceinline__ uint32_t bf16x2(float lo, float hi) {
    __nv_bfloat16 l = __float2bfloat16(lo), h = __float2bfloat16(hi);
    return ((uint32_t)__bfloat16_as_ushort(h) << 16) | __bfloat16_as_ushort(l);
}

// smem tiles, 144-byte row pitch (9x16B -> conflict-free ldmatrix, no swizzle)
#define AH_OFF 0u
#define AL_OFF 18432u
#define BH_OFF 36864u
#define BL_OFF 46080u
#define DSMEM  55296

#define LDSM4(r0, r1, r2, r3, a) \
    asm volatile("ldmatrix.sync.aligned.m8n8.x4.shared.b16 {%0,%1,%2,%3}, [%4];" \
                 : "=r"(r0), "=r"(r1), "=r"(r2), "=r"(r3) : "r"(a))

#define MMA16816(d, a, b0v, b1v) \
    asm volatile("mma.sync.aligned.m16n8k16.row.col.f32.bf16.bf16.f32 " \
                 "{%0,%1,%2,%3}, {%4,%5,%6,%7}, {%8,%9}, {%0,%1,%2,%3};" \
                 : "+f"(d[0]), "+f"(d[1]), "+f"(d[2]), "+f"(d[3]) \
                 : "r"(a[0]), "r"(a[1]), "r"(a[2]), "r"(a[3]), "r"(b0v), "r"(b1v))

__global__ void __launch_bounds__(128, 2) netc_kernel(
    const float* __restrict__ x, const float* __restrict__ y,
    const float* __restrict__ ex, const float* __restrict__ ey,
    const float* __restrict__ W1, const float* __restrict__ b1,
    const float* __restrict__ W2, const float* __restrict__ b2,
    const float* __restrict__ W3, const float* __restrict__ b3,
    float* __restrict__ out, int n, int ntiles) {
    extern __shared__ char dsm[];
    __shared__ float w1s[128], b1s[64], b2s[64], w3s[64];
    __shared__ float usx[128];  // per-token u exchange

    unsigned base = (unsigned)__cvta_generic_to_shared(dsm);
    int tid = threadIdx.x;
    int lane = tid & 31, wid = tid >> 5;
    int q = lane & 3, g = lane >> 2;

    w1s[tid] = W1[tid];
    if (tid < 64) { b1s[tid] = b1[tid]; b2s[tid] = b2[tid]; w3s[tid] = W3[tid]; }

    // W2 -> bf16 hi/lo B tiles (once per persistent CTA).
    for (int p = tid; p < 2048; p += 128) {
        int j = p >> 5, kw = p & 31;
        float2 v = ((const float2*)W2)[p];
        __nv_bfloat16 hx = __float2bfloat16(v.x);
        __nv_bfloat16 hy = __float2bfloat16(v.y);
        float fx = __bfloat162float(hx), fy = __bfloat162float(hy);
        uint32_t whi = ((uint32_t)__bfloat16_as_ushort(hy) << 16) | __bfloat16_as_ushort(hx);
        uint32_t wlo = bf16x2(v.x - fx, v.y - fy);
        unsigned off = (unsigned)(j * 144 + kw * 4);
        asm volatile("st.shared.b32 [%0], %1;" :: "r"(base + BH_OFF + off), "r"(whi) : "memory");
        asm volatile("st.shared.b32 [%0], %1;" :: "r"(base + BL_OFF + off), "r"(wlo) : "memory");
    }
    __syncthreads();

    float ut = g_u_tgt, bias3 = b3[0];

    // ldmatrix lane addressing
    int a_row_in = (lane & 15);
    int a_koff = (lane >> 4) * 16;
    int b_row = (lane & 7);
    int b_coff = (lane >> 3) * 16;

    // Prefetch tile 0 inputs.
    int tile = blockIdx.x;
    int mytok = tile * 128 + tid;
    int ic = min(mytok, n - 1);
    float xv = x[ic], yv = y[ic], exv = ex[ic], eyv = ey[ic];

    for (; tile < ntiles; tile += gridDim.x) {
        int token0 = tile * 128;
        mytok = token0 + tid;

        // ---- layer 1 (fp32) for this lane's token, split to bf16 hi/lo A rows ----
        float av = xv + exv, cv = yv + eyv;
        float h[64];
#pragma unroll
        for (int k = 0; k < 64; k++)
            h[k] = fmaxf(fmaf(w1s[2 * k], av, fmaf(w1s[2 * k + 1], cv, b1s[k])), 0.f);

#pragma unroll
        for (int c4 = 0; c4 < 8; c4++) {
            uint32_t hiw[4], low[4];
#pragma unroll
            for (int w = 0; w < 4; w++) {
                int kw = c4 * 4 + w;
                float v0 = h[2 * kw], v1 = h[2 * kw + 1];
                __nv_bfloat16 h0 = __float2bfloat16(v0), h1 = __float2bfloat16(v1);
                float f0 = __bfloat162float(h0), f1 = __bfloat162float(h1);
                hiw[w] = ((uint32_t)__bfloat16_as_ushort(h1) << 16) | __bfloat16_as_ushort(h0);
                low[w] = bf16x2(v0 - f0, v1 - f1);
            }
            unsigned off = (unsigned)(tid * 144 + c4 * 16);
            asm volatile("st.shared.v4.b32 [%0], {%1,%2,%3,%4};"
                         :: "r"(base + AH_OFF + off), "r"(hiw[0]), "r"(hiw[1]), "r"(hiw[2]), "r"(hiw[3]) : "memory");
            asm volatile("st.shared.v4.b32 [%0], {%1,%2,%3,%4};"
                         :: "r"(base + AL_OFF + off), "r"(low[0]), "r"(low[1]), "r"(low[2]), "r"(low[3]) : "memory");
        }
        __syncwarp();

        // Prefetch next tile's inputs (hide LDG under GEMM).
        float nxv = xv, nyv = yv, nexv = exv, neyv = eyv;
        int ntile = tile + gridDim.x;
        if (ntile < ntiles) {
            int nic = min(ntile * 128 + tid, n - 1);
            nxv = x[nic]; nyv = y[nic]; nexv = ex[nic]; neyv = ey[nic];
        }

        // ---- GEMM: 2 m-tiles x 8 n-tiles, 3 compensated splits ----
        float d[2][8][4];
#pragma unroll
        for (int mt = 0; mt < 2; mt++)
#pragma unroll
            for (int nt = 0; nt < 8; nt++)
#pragma unroll
                for (int r = 0; r < 4; r++) d[mt][nt][r] = 0.f;

#pragma unroll
        for (int split = 0; split < 3; split++) {
            unsigned abase = base + ((split == 2) ? AL_OFF : AH_OFF);
            unsigned bbase = base + ((split == 1) ? BL_OFF : BH_OFF);

            uint32_t bfr[8][8];
#pragma unroll
            for (int nt = 0; nt < 8; nt++) {
#pragma unroll
                for (int ksp = 0; ksp < 2; ksp++) {
                    unsigned addr = bbase + (unsigned)((nt * 8 + b_row) * 144 + ksp * 64) + b_coff;
                    LDSM4(bfr[nt][ksp * 4 + 0], bfr[nt][ksp * 4 + 1],
                          bfr[nt][ksp * 4 + 2], bfr[nt][ksp * 4 + 3], addr);
                }
            }
#pragma unroll
            for (int mt = 0; mt < 2; mt++) {
                uint32_t afr[4][4];
#pragma unroll
                for (int ks = 0; ks < 4; ks++) {
                    int row = wid * 32 + mt * 16 + a_row_in;
                    unsigned addr = abase + (unsigned)(row * 144 + ks * 32) + a_koff;
                    LDSM4(afr[ks][0], afr[ks][1], afr[ks][2], afr[ks][3], addr);
                }
#pragma unroll
                for (int nt = 0; nt < 8; nt++) {
#pragma unroll
                    for (int ks = 0; ks < 4; ks++) {
                        int bi = (ks >> 1) * 4 + (ks & 1) * 2;
                        MMA16816(d[mt][nt], afr[ks], bfr[nt][bi], bfr[nt][bi + 1]);
                    }
                }
            }
        }

        // ---- layer 3 reduction; exchange u through smem for coalesced stores ----
#pragma unroll
        for (int mt = 0; mt < 2; mt++) {
            float s0 = 0.f, s1 = 0.f;
#pragma unroll
            for (int nt = 0; nt < 8; nt++) {
                int j0 = nt * 8 + 2 * q, j1 = j0 + 1;
                float w30 = w3s[j0], w31 = w3s[j1];
                float b20 = b2s[j0], b21 = b2s[j1];
                s0 = fmaf(w30, fmaxf(d[mt][nt][0] + b20, 0.f), s0);
                s0 = fmaf(w31, fmaxf(d[mt][nt][1] + b21, 0.f), s0);
                s1 = fmaf(w30, fmaxf(d[mt][nt][2] + b20, 0.f), s1);
                s1 = fmaf(w31, fmaxf(d[mt][nt][3] + b21, 0.f), s1);
            }
            s0 += __shfl_xor_sync(0xffffffffu, s0, 1);
            s0 += __shfl_xor_sync(0xffffffffu, s0, 2);
            s1 += __shfl_xor_sync(0xffffffffu, s1, 1);
            s1 += __shfl_xor_sync(0xffffffffu, s1, 2);
            if (q == 0) {
                usx[wid * 32 + mt * 16 + g] = s0;
                usx[wid * 32 + mt * 16 + g + 8] = s1;
            }
        }
        __syncwarp();

        // Hill epilogue: one token per lane, fully coalesced stores.
        if (mytok < n) {
            float u = usx[tid] + bias3 - ut;
            float xs = xv * 0.1f, ys = yv * 0.1f;
            float x2 = xs * xs, y2 = ys * ys;
            float ivx = 1.f / (0.25f + x2);
            float ivy = 1.f / (0.25f + y2);
            float hx = x2 * ivx, hy = y2 * ivy;
            float gx = 0.25f * ivx, gy = 0.25f * ivy;
            float dx = 10.f * (hx + 0.2f * gy - 1.1f * xs + u * hx);
            float dy = 10.f * (hy + 0.2f * gx - 1.1f * ys);
            out[mytok] = dx;
            out[n + mytok] = dy;
            out[2 * n + mytok] = -dx;
            out[3 * n + mytok] = -dy;
        }
        __syncwarp();  // protect A tile + usx before next iteration

        xv = nxv; yv = nyv; exv = nexv; eyv = neyv;
    }
}

extern "C" void kernel_launch(void* const* d_in, const int* in_sizes, int n_in,
                              void* d_out, int out_size) {
    const float* x  = (const float*)d_in[0];
    const float* y  = (const float*)d_in[1];
    const float* ex = (const float*)d_in[2];
    const float* ey = (const float*)d_in[3];
    const float* W1 = (const float*)d_in[4];
    const float* b1 = (const float*)d_in[5];
    const float* W2 = (const float*)d_in[6];
    const float* b2 = (const float*)d_in[7];
    const float* W3 = (const float*)d_in[8];
    const float* b3 = (const float*)d_in[9];
    int n = in_sizes[0];
    int ntiles = (n + 127) / 128;

    static bool attr_set = false;
    if (!attr_set) {
        cudaFuncSetAttribute(netc_kernel,
                             cudaFuncAttributeMaxDynamicSharedMemorySize, DSMEM);
        attr_set = true;
    }

    utgt_kernel<<<1, 64>>>(W1, b1, W2, b2, W3, b3);
    int blocks = 296;  // 2 persistent CTAs per SM
    if (blocks > ntiles) blocks = ntiles;
    netc_kernel<<<blocks, 128, DSMEM>>>(x, y, ex, ey, W1, b1, W2, b2, W3, b3,
                                        (float*)d_out, n, ntiles);
}

// round 9
// speedup vs baseline: 3.2504x; 1.0254x over previous
#include <cuda_runtime.h>
#include <cuda_bf16.h>
#include <cstdint>

__device__ float g_u_tgt;

// Compute u(target) = MLP(6.2562059, 6.2562059) once per launch.
__global__ void utgt_kernel(const float* __restrict__ W1, const float* __restrict__ b1,
                            const float* __restrict__ W2, const float* __restrict__ b2,
                            const float* __restrict__ W3, const float* __restrict__ b3) {
    __shared__ float h1[64];
    __shared__ float part[64];
    int t = threadIdx.x;
    const float tt = 6.2562059f;
    float h = fmaf(W1[2 * t], tt, fmaf(W1[2 * t + 1], tt, b1[t]));
    h1[t] = fmaxf(h, 0.f);
    __syncthreads();
    float acc = b2[t];
#pragma unroll
    for (int k = 0; k < 64; k++) acc = fmaf(W2[t * 64 + k], h1[k], acc);
    part[t] = W3[t] * fmaxf(acc, 0.f);
    __syncthreads();
    if (t == 0) {
        float s = b3[0];
#pragma unroll
        for (int k = 0; k < 64; k++) s += part[k];
        g_u_tgt = s;
    }
}

__device__ __forceinline__ uint32_t bf16x2(float lo, float hi) {
    __nv_bfloat16 l = __float2bfloat16(lo), h = __float2bfloat16(hi);
    return ((uint32_t)__bfloat16_as_ushort(h) << 16) | __bfloat16_as_ushort(l);
}

// B tiles only in dynamic smem, 144-byte row pitch (conflict-free ldmatrix)
#define BH_OFF 0u
#define BL_OFF 9216u
#define DSMEM  18432

#define LDSM4(r0, r1, r2, r3, a) \
    asm volatile("ldmatrix.sync.aligned.m8n8.x4.shared.b16 {%0,%1,%2,%3}, [%4];" \
                 : "=r"(r0), "=r"(r1), "=r"(r2), "=r"(r3) : "r"(a))

#define MMA16816(d, a, b0v, b1v) \
    asm volatile("mma.sync.aligned.m16n8k16.row.col.f32.bf16.bf16.f32 " \
                 "{%0,%1,%2,%3}, {%4,%5,%6,%7}, {%8,%9}, {%0,%1,%2,%3};" \
                 : "+f"(d[0]), "+f"(d[1]), "+f"(d[2]), "+f"(d[3]) \
                 : "r"(a[0]), "r"(a[1]), "r"(a[2]), "r"(a[3]), "r"(b0v), "r"(b1v))

__global__ void __launch_bounds__(128) netc_kernel(
    const float* __restrict__ x, const float* __restrict__ y,
    const float* __restrict__ ex, const float* __restrict__ ey,
    const float* __restrict__ W1, const float* __restrict__ b1,
    const float* __restrict__ W2, const float* __restrict__ b2,
    const float* __restrict__ W3, const float* __restrict__ b3,
    float* __restrict__ out, int n, int ntiles) {
    extern __shared__ char dsm[];
    __shared__ float w1s[128], b1s[64], b2s[64], w3s[64];
    __shared__ float usx[128];

    unsigned base = (unsigned)__cvta_generic_to_shared(dsm);
    int tid = threadIdx.x;
    int lane = tid & 31, wid = tid >> 5;
    int q = lane & 3, g = lane >> 2;

    w1s[tid] = W1[tid];
    if (tid < 64) { b1s[tid] = b1[tid]; b2s[tid] = b2[tid]; w3s[tid] = W3[tid]; }

    // W2 -> bf16 hi/lo B tiles (once per persistent CTA).
    for (int p = tid; p < 2048; p += 128) {
        int j = p >> 5, kw = p & 31;
        float2 v = ((const float2*)W2)[p];
        __nv_bfloat16 hx = __float2bfloat16(v.x);
        __nv_bfloat16 hy = __float2bfloat16(v.y);
        float fx = __bfloat162float(hx), fy = __bfloat162float(hy);
        uint32_t whi = ((uint32_t)__bfloat16_as_ushort(hy) << 16) | __bfloat16_as_ushort(hx);
        uint32_t wlo = bf16x2(v.x - fx, v.y - fy);
        unsigned off = (unsigned)(j * 144 + kw * 4);
        asm volatile("st.shared.b32 [%0], %1;" :: "r"(base + BH_OFF + off), "r"(whi) : "memory");
        asm volatile("st.shared.b32 [%0], %1;" :: "r"(base + BL_OFF + off), "r"(wlo) : "memory");
    }
    __syncthreads();

    float ut = g_u_tgt, bias3 = b3[0];
    int b_row = lane & 7, b_coff = (lane >> 3) * 16;

    // Per-lane layer-1 weights for the 16 fragment k-columns (loop-invariant).
    // li = ks*4 + b -> kk = ks*16 + (b>>1)*8 + q*2 + (b&1)
    float wAr[16], wBr[16], bbr[16];
#pragma unroll
    for (int li = 0; li < 16; li++) {
        int kk = (li >> 2) * 16 + ((li >> 1) & 1) * 8 + q * 2 + (li & 1);
        wAr[li] = w1s[2 * kk];
        wBr[li] = w1s[2 * kk + 1];
        bbr[li] = b1s[kk];
    }

    // Preload tile-0 inputs for this lane's 4 fragment token-rows.
    int tile = blockIdx.x;
    float ain[2][2], cin[2][2];
    {
        int tb = tile * 128 + wid * 32 + g;
#pragma unroll
        for (int mt = 0; mt < 2; mt++)
#pragma unroll
            for (int hf = 0; hf < 2; hf++) {
                int idx = min(tb + mt * 16 + hf * 8, n - 1);
                ain[mt][hf] = x[idx] + ex[idx];
                cin[mt][hf] = y[idx] + ey[idx];
            }
    }

    for (; tile < ntiles; tile += gridDim.x) {
        int token0 = tile * 128;
        int mytok = token0 + tid;

        // ---- layer 1 + bf16 hi/lo A fragments, all in registers ----
        uint32_t Ah[2][4][4], Al[2][4][4];
#pragma unroll
        for (int mt = 0; mt < 2; mt++) {
#pragma unroll
            for (int hf = 0; hf < 2; hf++) {
                float av = ain[mt][hf], cv = cin[mt][hf];
#pragma unroll
                for (int ks = 0; ks < 4; ks++) {
                    float v0 = fmaxf(fmaf(wAr[ks * 4 + 0], av, fmaf(wBr[ks * 4 + 0], cv, bbr[ks * 4 + 0])), 0.f);
                    float v1 = fmaxf(fmaf(wAr[ks * 4 + 1], av, fmaf(wBr[ks * 4 + 1], cv, bbr[ks * 4 + 1])), 0.f);
                    float v2 = fmaxf(fmaf(wAr[ks * 4 + 2], av, fmaf(wBr[ks * 4 + 2], cv, bbr[ks * 4 + 2])), 0.f);
                    float v3 = fmaxf(fmaf(wAr[ks * 4 + 3], av, fmaf(wBr[ks * 4 + 3], cv, bbr[ks * 4 + 3])), 0.f);
                    uint32_t h01, h23, l01, l23;
                    asm("cvt.rn.bf16x2.f32 %0, %1, %2;" : "=r"(h01) : "f"(v1), "f"(v0));
                    asm("cvt.rn.bf16x2.f32 %0, %1, %2;" : "=r"(h23) : "f"(v3), "f"(v2));
                    float f0 = __uint_as_float(h01 << 16);
                    float f1 = __uint_as_float(h01 & 0xffff0000u);
                    float f2 = __uint_as_float(h23 << 16);
                    float f3 = __uint_as_float(h23 & 0xffff0000u);
                    asm("cvt.rn.bf16x2.f32 %0, %1, %2;" : "=r"(l01) : "f"(v1 - f1), "f"(v0 - f0));
                    asm("cvt.rn.bf16x2.f32 %0, %1, %2;" : "=r"(l23) : "f"(v3 - f3), "f"(v2 - f2));
                    Ah[mt][ks][hf] = h01;
                    Ah[mt][ks][2 + hf] = h23;
                    Al[mt][ks][hf] = l01;
                    Al[mt][ks][2 + hf] = l23;
                }
            }
        }

        // Prefetch next tile's inputs (hidden under the GEMM).
        float na[2][2], nc[2][2];
        int ntile = tile + gridDim.x;
        if (ntile < ntiles) {
            int tb = ntile * 128 + wid * 32 + g;
#pragma unroll
            for (int mt = 0; mt < 2; mt++)
#pragma unroll
                for (int hf = 0; hf < 2; hf++) {
                    int idx = min(tb + mt * 16 + hf * 8, n - 1);
                    na[mt][hf] = x[idx] + ex[idx];
                    nc[mt][hf] = y[idx] + ey[idx];
                }
        } else {
#pragma unroll
            for (int mt = 0; mt < 2; mt++)
#pragma unroll
                for (int hf = 0; hf < 2; hf++) { na[mt][hf] = ain[mt][hf]; nc[mt][hf] = cin[mt][hf]; }
        }

        // ---- GEMM: 3 compensated splits; B streamed per n-tile from smem ----
        float d[2][8][4];
#pragma unroll
        for (int mt = 0; mt < 2; mt++)
#pragma unroll
            for (int nt = 0; nt < 8; nt++)
#pragma unroll
                for (int r = 0; r < 4; r++) d[mt][nt][r] = 0.f;

#pragma unroll
        for (int split = 0; split < 3; split++) {
            const uint32_t (*Af)[4][4] = (split == 2) ? Al : Ah;
            unsigned bbase = base + ((split == 1) ? BL_OFF : BH_OFF);
#pragma unroll
            for (int nt = 0; nt < 8; nt++) {
                uint32_t bfr[8];
                unsigned addr = bbase + (unsigned)((nt * 8 + b_row) * 144) + b_coff;
                LDSM4(bfr[0], bfr[1], bfr[2], bfr[3], addr);
                LDSM4(bfr[4], bfr[5], bfr[6], bfr[7], addr + 64);
#pragma unroll
                for (int mt = 0; mt < 2; mt++) {
#pragma unroll
                    for (int ks = 0; ks < 4; ks++) {
                        int bi = (ks >> 1) * 4 + (ks & 1) * 2;
                        MMA16816(d[mt][nt], Af[mt][ks], bfr[bi], bfr[bi + 1]);
                    }
                }
            }
        }

        // ---- layer 3 reduction; exchange u through smem for coalesced stores ----
#pragma unroll
        for (int mt = 0; mt < 2; mt++) {
            float s0 = 0.f, s1 = 0.f;
#pragma unroll
            for (int nt = 0; nt < 8; nt++) {
                int j0 = nt * 8 + 2 * q, j1 = j0 + 1;
                float w30 = w3s[j0], w31 = w3s[j1];
                float b20 = b2s[j0], b21 = b2s[j1];
                s0 = fmaf(w30, fmaxf(d[mt][nt][0] + b20, 0.f), s0);
                s0 = fmaf(w31, fmaxf(d[mt][nt][1] + b21, 0.f), s0);
                s1 = fmaf(w30, fmaxf(d[mt][nt][2] + b20, 0.f), s1);
                s1 = fmaf(w31, fmaxf(d[mt][nt][3] + b21, 0.f), s1);
            }
            s0 += __shfl_xor_sync(0xffffffffu, s0, 1);
            s0 += __shfl_xor_sync(0xffffffffu, s0, 2);
            s1 += __shfl_xor_sync(0xffffffffu, s1, 1);
            s1 += __shfl_xor_sync(0xffffffffu, s1, 2);
            if (q == 0) {
                usx[wid * 32 + mt * 16 + g] = s0;
                usx[wid * 32 + mt * 16 + g + 8] = s1;
            }
        }
        __syncwarp();

        if (mytok < n) {
            float xv = x[mytok], yv = y[mytok];   // L1 hits (warp range just touched)
            float u = usx[tid] + bias3 - ut;
            float xs = xv * 0.1f, ys = yv * 0.1f;
            float x2 = xs * xs, y2 = ys * ys;
            float ivx = 1.f / (0.25f + x2);
            float ivy = 1.f / (0.25f + y2);
            float hx = x2 * ivx, hy = y2 * ivy;
            float gx = 0.25f * ivx, gy = 0.25f * ivy;
            float dx = 10.f * (hx + 0.2f * gy - 1.1f * xs + u * hx);
            float dy = 10.f * (hy + 0.2f * gx - 1.1f * ys);
            out[mytok] = dx;
            out[n + mytok] = dy;
            out[2 * n + mytok] = -dx;
            out[3 * n + mytok] = -dy;
        }
        __syncwarp();  // usx reuse guard

#pragma unroll
        for (int mt = 0; mt < 2; mt++)
#pragma unroll
            for (int hf = 0; hf < 2; hf++) { ain[mt][hf] = na[mt][hf]; cin[mt][hf] = nc[mt][hf]; }
    }
}

extern "C" void kernel_launch(void* const* d_in, const int* in_sizes, int n_in,
                              void* d_out, int out_size) {
    const float* x  = (const float*)d_in[0];
    const float* y  = (const float*)d_in[1];
    const float* ex = (const float*)d_in[2];
    const float* ey = (const float*)d_in[3];
    const float* W1 = (const float*)d_in[4];
    const float* b1 = (const float*)d_in[5];
    const float* W2 = (const float*)d_in[6];
    const float* b2 = (const float*)d_in[7];
    const float* W3 = (const float*)d_in[8];
    const float* b3 = (const float*)d_in[9];
    int n = in_sizes[0];
    int ntiles = (n + 127) / 128;

    utgt_kernel<<<1, 64>>>(W1, b1, W2, b2, W3, b3);
    int blocks = 296;  // 2 persistent CTAs per SM
    if (blocks > ntiles) blocks = ntiles;
    netc_kernel<<<blocks, 128, DSMEM>>>(x, y, ex, ey, W1, b1, W2, b2, W3, b3,
                                        (float*)d_out, n, ntiles);
}